// round 1
// baseline (speedup 1.0000x reference)
#include <cuda_runtime.h>
#include <math.h>

#define NFEAT 256
#define NHID  128
#define NCLASS 16
#define MAXN 100000
#define MAXE 3200000

// ---------------- device scratch (static allocation, allowed) ----------------
__device__ float g_H0[(size_t)MAXN * NHID];   // x @ W1
__device__ float g_H1[(size_t)MAXN * NHID];   // relu(spmm1 + b1)
__device__ float g_H2[(size_t)MAXN * NCLASS]; // H1 @ W2
__device__ int   g_offs[MAXN + 1];
__device__ int   g_cursor[MAXN];
__device__ int   g_esrc[MAXE];
__device__ float g_ews[MAXE];
__device__ int   g_bsum[512];
__device__ int   g_bexc[512];

// ---------------- helpers ----------------
__device__ __forceinline__ void ffma2(float2& d, float2 a, float2 b) {
    unsigned long long& ud = reinterpret_cast<unsigned long long&>(d);
    unsigned long long  ua = reinterpret_cast<unsigned long long&>(a);
    unsigned long long  ub = reinterpret_cast<unsigned long long&>(b);
    asm("fma.rn.f32x2 %0, %1, %2, %0;" : "+l"(ud) : "l"(ua), "l"(ub));
}

__device__ __forceinline__ int block_incl_scan(int v, int* swarp, int nwarps) {
    int lane = threadIdx.x & 31, wid = threadIdx.x >> 5;
    #pragma unroll
    for (int o = 1; o < 32; o <<= 1) {
        int n = __shfl_up_sync(0xffffffffu, v, o);
        if (lane >= o) v += n;
    }
    if (lane == 31) swarp[wid] = v;
    __syncthreads();
    if (wid == 0) {
        int s = (lane < nwarps) ? swarp[lane] : 0;
        #pragma unroll
        for (int o = 1; o < 32; o <<= 1) {
            int n = __shfl_up_sync(0xffffffffu, s, o);
            if (lane >= o) s += n;
        }
        swarp[lane] = s;
    }
    __syncthreads();
    if (wid > 0) v += swarp[wid - 1];
    return v;
}

// ---------------- CSR construction ----------------
__global__ void zero_offs_kernel(int L) {
    int i = blockIdx.x * blockDim.x + threadIdx.x;
    if (i < L) g_offs[i] = 0;
}

__global__ void degree_kernel(const int* __restrict__ dst, int E) {
    int e = blockIdx.x * blockDim.x + threadIdx.x;
    if (e < E) atomicAdd(&g_offs[dst[e] + 1], 1);
}

__global__ void scan_block_sums(int L) {
    __shared__ int sw[32];
    int i = blockIdx.x * blockDim.x + threadIdx.x;
    int v = (i < L) ? g_offs[i] : 0;
    int incl = block_incl_scan(v, sw, blockDim.x >> 5);
    if (threadIdx.x == blockDim.x - 1) g_bsum[blockIdx.x] = incl;
}

__global__ void scan_partials(int NB) {
    __shared__ int sw[32];
    int t = threadIdx.x;
    int v = (t < NB) ? g_bsum[t] : 0;
    int incl = block_incl_scan(v, sw, blockDim.x >> 5);
    g_bexc[t] = incl - v;  // exclusive prefix of block sums
}

__global__ void scan_apply(int L) {
    __shared__ int sw[32];
    int i = blockIdx.x * blockDim.x + threadIdx.x;
    int v = (i < L) ? g_offs[i] : 0;
    int incl = block_incl_scan(v, sw, blockDim.x >> 5);
    if (i < L) {
        int val = incl + g_bexc[blockIdx.x];
        g_offs[i] = val;
        if (i < L - 1) g_cursor[i] = val;  // row start cursors for fill
    }
}

__global__ void fill_csr(const int* __restrict__ src, const int* __restrict__ dst,
                         const float* __restrict__ w, int E) {
    int e = blockIdx.x * blockDim.x + threadIdx.x;
    if (e >= E) return;
    int d = dst[e];
    int p = atomicAdd(&g_cursor[d], 1);
    g_esrc[p] = src[e];
    g_ews[p]  = w[e];
}

// ---------------- GEMM1: H0 = x @ W1  (N x 256 x 128, fp32 via f32x2 FMA) ----------------
__global__ void gemm1_kernel(const float* __restrict__ X, const float* __restrict__ W, int N) {
    __shared__ float As[16][128];  // x tile, transposed: As[k][row]
    __shared__ float Bs[16][128];  // W tile: Bs[k][col]
    const int tid = threadIdx.x;
    const int tx = tid & 15;   // col group -> cols [tx*8, tx*8+8)
    const int ty = tid >> 4;   // row group -> rows [ty*8, ty*8+8)
    const int bRow = blockIdx.x * 128;

    float2 acc[8][4];
    #pragma unroll
    for (int r = 0; r < 8; r++)
        #pragma unroll
        for (int c = 0; c < 4; c++) acc[r][c] = make_float2(0.f, 0.f);

    for (int kt = 0; kt < NFEAT; kt += 16) {
        #pragma unroll
        for (int i = 0; i < 2; i++) {
            int idx = tid + i * 256;                // [0,512)
            int ar = idx >> 2, akq = idx & 3;       // A: 128 rows x 4 k-quads
            float4 av = make_float4(0.f, 0.f, 0.f, 0.f);
            int grow = bRow + ar;
            if (grow < N)
                av = *reinterpret_cast<const float4*>(&X[(size_t)grow * NFEAT + kt + akq * 4]);
            As[akq * 4 + 0][ar] = av.x;
            As[akq * 4 + 1][ar] = av.y;
            As[akq * 4 + 2][ar] = av.z;
            As[akq * 4 + 3][ar] = av.w;
            int bk = idx >> 5, bc = (idx & 31) << 2; // B: 16 k-rows x 32 col-quads
            *reinterpret_cast<float4*>(&Bs[bk][bc]) =
                *reinterpret_cast<const float4*>(&W[(size_t)(kt + bk) * NHID + bc]);
        }
        __syncthreads();
        #pragma unroll
        for (int k = 0; k < 16; k++) {
            float a[8];
            *reinterpret_cast<float4*>(&a[0]) = *reinterpret_cast<const float4*>(&As[k][ty * 8]);
            *reinterpret_cast<float4*>(&a[4]) = *reinterpret_cast<const float4*>(&As[k][ty * 8 + 4]);
            float2 b[4];
            *reinterpret_cast<float4*>(&b[0]) = *reinterpret_cast<const float4*>(&Bs[k][tx * 8]);
            *reinterpret_cast<float4*>(&b[2]) = *reinterpret_cast<const float4*>(&Bs[k][tx * 8 + 4]);
            #pragma unroll
            for (int r = 0; r < 8; r++) {
                float2 ad = make_float2(a[r], a[r]);
                #pragma unroll
                for (int c = 0; c < 4; c++) ffma2(acc[r][c], ad, b[c]);
            }
        }
        __syncthreads();
    }
    #pragma unroll
    for (int r = 0; r < 8; r++) {
        int grow = bRow + ty * 8 + r;
        if (grow < N) {
            float4 o0 = make_float4(acc[r][0].x, acc[r][0].y, acc[r][1].x, acc[r][1].y);
            float4 o1 = make_float4(acc[r][2].x, acc[r][2].y, acc[r][3].x, acc[r][3].y);
            float* outp = &g_H0[(size_t)grow * NHID + tx * 8];
            *reinterpret_cast<float4*>(outp)     = o0;
            *reinterpret_cast<float4*>(outp + 4) = o1;
        }
    }
}

// ---------------- SPMM1 + bias + relu: H1 = relu(A @ H0 + b1) ----------------
// warp per dst row; lane holds float4 (4 of 128 cols); coalesced 512B row gathers.
__global__ void spmm1_kernel(const float* __restrict__ b1, int N) {
    int warp = (blockIdx.x * blockDim.x + threadIdx.x) >> 5;
    int lane = threadIdx.x & 31;
    if (warp >= N) return;
    int beg = g_offs[warp], end = g_offs[warp + 1];
    const float4* H04 = reinterpret_cast<const float4*>(g_H0);
    float4 acc = make_float4(0.f, 0.f, 0.f, 0.f);
    int e = beg;
    for (; e + 1 < end; e += 2) {
        int   s0 = g_esrc[e],   s1 = g_esrc[e + 1];
        float w0 = g_ews[e],    w1 = g_ews[e + 1];
        float4 v0 = H04[(size_t)s0 * 32 + lane];
        float4 v1 = H04[(size_t)s1 * 32 + lane];
        acc.x = fmaf(w0, v0.x, acc.x); acc.y = fmaf(w0, v0.y, acc.y);
        acc.z = fmaf(w0, v0.z, acc.z); acc.w = fmaf(w0, v0.w, acc.w);
        acc.x = fmaf(w1, v1.x, acc.x); acc.y = fmaf(w1, v1.y, acc.y);
        acc.z = fmaf(w1, v1.z, acc.z); acc.w = fmaf(w1, v1.w, acc.w);
    }
    if (e < end) {
        int s0 = g_esrc[e]; float w0 = g_ews[e];
        float4 v0 = H04[(size_t)s0 * 32 + lane];
        acc.x = fmaf(w0, v0.x, acc.x); acc.y = fmaf(w0, v0.y, acc.y);
        acc.z = fmaf(w0, v0.z, acc.z); acc.w = fmaf(w0, v0.w, acc.w);
    }
    float4 bb = reinterpret_cast<const float4*>(b1)[lane];
    float4 h;
    h.x = fmaxf(acc.x + bb.x, 0.f);
    h.y = fmaxf(acc.y + bb.y, 0.f);
    h.z = fmaxf(acc.z + bb.z, 0.f);
    h.w = fmaxf(acc.w + bb.w, 0.f);
    reinterpret_cast<float4*>(g_H1)[(size_t)warp * 32 + lane] = h;
}

// ---------------- GEMM2: H2 = H1 @ W2  (128 -> 16) ----------------
__global__ void gemm2_kernel(const float* __restrict__ W2, int N) {
    __shared__ float w[NHID * NCLASS];
    for (int i = threadIdx.x; i < NHID * NCLASS; i += blockDim.x) w[i] = W2[i];
    __syncthreads();
    int t = blockIdx.x * blockDim.x + threadIdx.x;
    int row = t >> 4, col = t & 15;
    if (row >= N) return;
    const float4* hr = reinterpret_cast<const float4*>(&g_H1[(size_t)row * NHID]);
    float acc = 0.f;
    #pragma unroll
    for (int k4 = 0; k4 < NHID / 4; k4++) {
        float4 hv = __ldg(&hr[k4]);
        acc = fmaf(hv.x, w[(k4 * 4 + 0) * NCLASS + col], acc);
        acc = fmaf(hv.y, w[(k4 * 4 + 1) * NCLASS + col], acc);
        acc = fmaf(hv.z, w[(k4 * 4 + 2) * NCLASS + col], acc);
        acc = fmaf(hv.w, w[(k4 * 4 + 3) * NCLASS + col], acc);
    }
    g_H2[(size_t)row * NCLASS + col] = acc;
}

// ---------------- SPMM2 + bias + log_softmax, fused ----------------
// half-warp per dst row: lanes l=0..15 hold the 16 classes.
__global__ void spmm2_kernel(const float* __restrict__ b2, float* __restrict__ out, int N) {
    int gwarp = (blockIdx.x * blockDim.x + threadIdx.x) >> 5;
    int lane = threadIdx.x & 31;
    int half = lane >> 4, l = lane & 15;
    int row = gwarp * 2 + half;
    float acc = 0.f;
    if (row < N) {
        int beg = g_offs[row], end = g_offs[row + 1];
        for (int e = beg; e < end; e++) {
            int s = g_esrc[e]; float w = g_ews[e];
            acc = fmaf(w, __ldg(&g_H2[(size_t)s * NCLASS + l]), acc);
        }
    }
    acc += b2[l];
    float m = acc;
    #pragma unroll
    for (int o = 8; o > 0; o >>= 1) m = fmaxf(m, __shfl_xor_sync(0xffffffffu, m, o, 16));
    float ex = expf(acc - m);
    float s = ex;
    #pragma unroll
    for (int o = 8; o > 0; o >>= 1) s += __shfl_xor_sync(0xffffffffu, s, o, 16);
    if (row < N) out[(size_t)row * NCLASS + l] = acc - m - logf(s);
}

// ---------------- launch ----------------
extern "C" void kernel_launch(void* const* d_in, const int* in_sizes, int n_in,
                              void* d_out, int out_size) {
    const float* x   = (const float*)d_in[0];
    const float* W1  = (const float*)d_in[1];
    const float* b1  = (const float*)d_in[2];
    const float* W2  = (const float*)d_in[3];
    const float* b2  = (const float*)d_in[4];
    const float* ew  = (const float*)d_in[5];
    const int*   src = (const int*)d_in[6];
    const int*   dst = (const int*)d_in[7];
    float* out = (float*)d_out;

    const int N = in_sizes[0] / NFEAT;
    const int E = in_sizes[5];
    const int L = N + 1;
    const int NB = (L + 255) / 256;   // <= 512

    // CSR build (by dst)
    zero_offs_kernel<<<(L + 255) / 256, 256>>>(L);
    degree_kernel<<<(E + 255) / 256, 256>>>(dst, E);
    scan_block_sums<<<NB, 256>>>(L);
    scan_partials<<<1, 512>>>(NB);
    scan_apply<<<NB, 256>>>(L);
    fill_csr<<<(E + 255) / 256, 256>>>(src, dst, ew, E);

    // layer 1
    gemm1_kernel<<<(N + 127) / 128, 256>>>(x, W1, N);
    spmm1_kernel<<<(N + 7) / 8, 256>>>(b1, N);

    // layer 2 + log_softmax
    gemm2_kernel<<<(N * 16 + 255) / 256, 256>>>(W2, N);
    spmm2_kernel<<<(N + 15) / 16, 256>>>(b2, out, N);
}